// round 15
// baseline (speedup 1.0000x reference)
#include <cuda_runtime.h>
#include <cuda_bf16.h>
#include <math.h>

#define NB    32
#define NPG   256
#define GS    256
#define NCLASS 6
#define MIN_NORM 1e-15f
#define MAXN 0.996f

#define NTHREADS 512
#define GRID     (NB * 4)

typedef unsigned long long u64;

// ---------------- global scratch ----------------
__device__ float g_sx[NB * NPG];
__device__ float g_adj1[NB * 256 * 256];
__device__ float g_adj2[NB * 128 * 128];
__device__ float g_v  [NB * GS * 64];
__device__ float g_tA [NB * GS * 64];
__device__ float g_dis[NB * GS];
__device__ float g_score[NB * GS];

// ---------------- smem layout (floats) ----------------
#define SM_HB     0        // 192
#define SM_HBN2   192      // 4
#define SM_RED    196      // 16
#define SM_SORTS  212      // 256
#define SM_SORTID 468      // 256 (int)
#define SM_SELS   724      // 128 (int)
#define SM_VALS   852      // 128
#define SM_SA1    980      // 128
#define SM_SA2    1108     // 128
#define SM_X1R    1236     // 128
#define SM_X2R    1364     // 128
#define SM_X3R    1492     // 128
#define SM_XN     1620     // 64
#define SM_MLP0   1684     // 128
#define SM_MLP1   1812     // 64
#define SM_MLP2   1876     // 32
#define SM_SCR    1920
// SCR-relative union:
//   a_s at A_ADJ=17504:
//     L1: 64*260=16640 (scatter)  L2: 32*132 (new_adj_gl_sm)  L3: 16*68 (new_adj_sm)
//   v_s stagings [0,16384); pre_agg Wt+xh [0,17408); readout scratch [0,1024)
// TB (pooled features, smem-resident) after a_s: 128*64 floats
#define A_ADJ  17504
#define SM_TB  (1920 + A_ADJ + 64 * 260)
#define SM_TOTALF (SM_TB + 128 * 64)
#define SMEM_BYTES (SM_TOTALF * 4)

#define CARRIVE() asm volatile("barrier.cluster.arrive.aligned;" ::: "memory")
#define CWAIT()   asm volatile("barrier.cluster.wait.aligned;"   ::: "memory")
#define CSYNC() do { CARRIVE(); CWAIT(); } while (0)

// ---------------- helpers (EXACT math & EXACT reduction orders — everything
// upstream of topk must be bit-faithful: fast approximations (R7) AND even
// changed summation order in deg (R13) flipped top-k selections and broke
// correctness. Do not touch any arithmetic or reduction order here.) --------
__device__ __forceinline__ float artanh_f(float x) {
    x = fminf(fmaxf(x, -1.0f + 1e-7f), 1.0f - 1e-7f);
    return 0.5f * (log1pf(x) - log1pf(-x));
}
__device__ __forceinline__ float wred32(float v) {
    #pragma unroll
    for (int o = 16; o > 0; o >>= 1) v += __shfl_xor_sync(0xffffffffu, v, o);
    return v;
}
__device__ __forceinline__ float hwred16(float v) {
    v += __shfl_xor_sync(0xffffffffu, v, 8);
    v += __shfl_xor_sync(0xffffffffu, v, 4);
    v += __shfl_xor_sync(0xffffffffu, v, 2);
    v += __shfl_xor_sync(0xffffffffu, v, 1);
    return v;
}
__device__ __forceinline__ float red64(float v, float* red) {
    int tid = threadIdx.x;
    #pragma unroll
    for (int o = 16; o > 0; o >>= 1) v += __shfl_xor_sync(0xffffffffu, v, o);
    if ((tid & 31) == 0) red[tid >> 5] = v;
    __syncthreads();
    float r = red[(tid >> 6) * 2] + red[(tid >> 6) * 2 + 1];
    __syncthreads();
    return r;
}
__device__ __forceinline__ float dot4(float4 a, float4 b) {
    return a.x * b.x + a.y * b.y + a.z * b.z + a.w * b.w;
}
__device__ __forceinline__ u64 pk2(float a) {
    u64 r; asm("mov.b64 %0,{%1,%1};" : "=l"(r) : "f"(a)); return r;
}
__device__ __forceinline__ u64 f2fma(u64 a, u64 b, u64 c) {
    u64 d; asm("fma.rn.f32x2 %0,%1,%2,%3;" : "=l"(d) : "l"(a), "l"(b), "l"(c)); return d;
}
__device__ __forceinline__ float2 upk(u64 a) {
    float2 f; asm("mov.b64 {%0,%1},%2;" : "=f"(f.x), "=f"(f.y) : "l"(a)); return f;
}

// ---------------- phases ----------------

// v = logmap0(proj(mobius_add(proj(mobius_matvec(W, to_hyp(in))), hb)))
// `in`/`vout` may be global OR shared (generic pointers).
template<int IN, int NQ>
__device__ void pre_agg(const float* __restrict__ in,
                        const float* __restrict__ W,
                        const float* HBl, float hbn2v,
                        float* __restrict__ vout, float* SCR, float* XN) {
    constexpr int XHP = IN + 8;
    constexpr int NR = NQ / 16;
    float* Wt = SCR;
    float* xh = SCR + IN * 68;
    int tid = threadIdx.x, w = tid >> 5, lane = tid & 31;

    // Transpose W into Wt with smem-CONSECUTIVE writes (bank-conflict-free);
    // values/addresses identical to the old loop — only the thread<->element
    // mapping changed (bit-exact). Strided access moved to the global-read
    // side, where L2 is idle and MLP hides latency.
    for (int idx = tid; idx < 64 * IN; idx += NTHREADS) {
        int o = idx & 63, kk = idx >> 6;
        Wt[kk * 68 + o] = W[(size_t)o * IN + kk];
    }
    if (tid < NQ * 8) {
        int node = tid >> 3, j = tid & 7;
        constexpr int F4 = IN / 32;
        const float4* ur = (const float4*)(in + (size_t)node * IN) + j * F4;
        float4 u[F4];
        float s = 0.f;
        #pragma unroll
        for (int t = 0; t < F4; t++) { u[t] = ur[t]; s += dot4(u[t], u[t]); }
        s += __shfl_xor_sync(0xffffffffu, s, 4);
        s += __shfl_xor_sync(0xffffffffu, s, 2);
        s += __shfl_xor_sync(0xffffffffu, s, 1);
        float un = fmaxf(sqrtf(s), MIN_NORM);
        float tu = tanhf(un);
        float s0 = tu / un, xn = tu;
        if (tu > MAXN) { s0 *= MAXN / tu; xn = MAXN; }
        float4* xrow = (float4*)(xh + node * XHP) + j * F4;
        #pragma unroll
        for (int t = 0; t < F4; t++)
            xrow[t] = make_float4(u[t].x * s0, u[t].y * s0, u[t].z * s0, u[t].w * s0);
        if (j == 0) XN[node] = xn;
    }
    __syncthreads();

    u64 acc[NR];
    #pragma unroll
    for (int r = 0; r < NR; r++) acc[r] = 0ull;
    #pragma unroll 2
    for (int k0 = 0; k0 < IN; k0 += 4) {
        float4 a[NR];
        #pragma unroll
        for (int r = 0; r < NR; r++)
            a[r] = *(const float4*)(xh + (w * NR + r) * XHP + k0);
        u64 vv[4];
        #pragma unroll
        for (int j = 0; j < 4; j++)
            vv[j] = *(const u64*)(Wt + (k0 + j) * 68 + 2 * lane);
        #pragma unroll
        for (int r = 0; r < NR; r++) {
            acc[r] = f2fma(pk2(a[r].x), vv[0], acc[r]);
            acc[r] = f2fma(pk2(a[r].y), vv[1], acc[r]);
            acc[r] = f2fma(pk2(a[r].z), vv[2], acc[r]);
            acc[r] = f2fma(pk2(a[r].w), vv[3], acc[r]);
        }
    }
    float2 hb2 = *(const float2*)(HBl + 2 * lane);
    #pragma unroll
    for (int r = 0; r < NR; r++) {
        int node = w * NR + r;
        float2 mx = upk(acc[r]);
        float mxn = fmaxf(sqrtf(wred32(mx.x * mx.x + mx.y * mx.y)), MIN_NORM);
        float xnv = XN[node];
        float qv = mxn / xnv * artanh_f(xnv);
        float tq = tanhf(qv);
        float s1 = tq / mxn, hn = tq;
        if (tq > MAXN) { s1 *= MAXN / tq; hn = MAXN; }
        float2 hv = make_float2(mx.x * s1, mx.y * s1);
        float xy = wred32(hv.x * hb2.x + hv.y * hb2.y);
        float x2 = hn * hn, y2 = hbn2v;
        float ca = 1.f + 2.f * xy + y2, cb = 1.f - x2;
        float den = fmaxf(1.f + 2.f * xy + x2 * y2, MIN_NORM);
        float2 m = make_float2((ca * hv.x + cb * hb2.x) / den,
                               (ca * hv.y + cb * hb2.y) / den);
        float mn = fmaxf(sqrtf(wred32(m.x * m.x + m.y * m.y)), MIN_NORM);
        float s2 = 1.f, pn = mn;
        if (mn > MAXN) { s2 = MAXN / mn; pn = MAXN; }
        float lf = artanh_f(pn) / pn * s2;
        *(float2*)(vout + (size_t)node * 64 + 2 * lane) =
            make_float2(m.x * lf, m.y * lf);
    }
}

// adj@v -> nonlinear chain -> t; also dis for own quarter rows. a_s pre-filled.
// (deg pass MUST stay exactly in this lane-strided shuffle order — R13.)
template<int NPGc>
__device__ void agg(int q, const float* __restrict__ vg, float* __restrict__ tg,
                    float* __restrict__ disg, float* SCR) {
    constexpr int R = NPGc / 4;
    constexpr int AP = NPGc + 4;
    constexpr int NR = R / 16;
    float* v_s = SCR;
    float* a_s = SCR + A_ADJ;
    int tid = threadIdx.x, w = tid >> 5, lane = tid & 31;
    int rowb = q * R;

    { const float4* vg4 = (const float4*)vg; float4* v_s4 = (float4*)v_s;
      #pragma unroll 4
      for (int i = tid; i < NPGc * 16; i += NTHREADS) v_s4[i] = vg4[i]; }
    __syncthreads();

    #pragma unroll
    for (int rr = 0; rr < NR; rr++) {
        int r = w * NR + rr;
        float s = 0.f;
        #pragma unroll 4
        for (int k = lane; k < NPGc; k += 32) s += a_s[r * AP + k];
        s = wred32(s);
        if (lane == 0) disg[rowb + r] = (s > 0.f) ? (1.f / sqrtf(s)) : 0.f;
    }

    u64 acc[NR];
    #pragma unroll
    for (int r = 0; r < NR; r++) acc[r] = 0ull;
    #pragma unroll 2
    for (int k0 = 0; k0 < NPGc; k0 += 4) {
        float4 a[NR];
        #pragma unroll
        for (int r = 0; r < NR; r++)
            a[r] = *(const float4*)(a_s + (w * NR + r) * AP + k0);
        u64 vv[4];
        #pragma unroll
        for (int j = 0; j < 4; j++)
            vv[j] = *(const u64*)(v_s + (k0 + j) * 64 + 2 * lane);
        #pragma unroll
        for (int r = 0; r < NR; r++) {
            acc[r] = f2fma(pk2(a[r].x), vv[0], acc[r]);
            acc[r] = f2fma(pk2(a[r].y), vv[1], acc[r]);
            acc[r] = f2fma(pk2(a[r].z), vv[2], acc[r]);
            acc[r] = f2fma(pk2(a[r].w), vv[3], acc[r]);
        }
    }
    #pragma unroll
    for (int r = 0; r < NR; r++) {
        float2 y = upk(acc[r]);
        float an = fmaxf(sqrtf(wred32(y.x * y.x + y.y * y.y)), MIN_NORM);
        float ta = tanhf(an);
        float s1 = ta / an, hn = ta;
        if (ta > MAXN) { s1 *= MAXN / ta; hn = MAXN; }
        float lf = artanh_f(hn) / hn * s1;
        float2 rr2 = make_float2(fmaxf(y.x * lf, 0.f), fmaxf(y.y * lf, 0.f));
        float rn = fmaxf(sqrtf(wred32(rr2.x * rr2.x + rr2.y * rr2.y)), MIN_NORM);
        float tr = tanhf(rn);
        float s2 = tr / rn, en = tr;
        if (tr > MAXN) { s2 *= MAXN / tr; en = MAXN; }
        float tf = artanh_f(en) / en * s2;
        *(float2*)(tg + (size_t)(rowb + w * NR + r) * 64 + 2 * lane) =
            make_float2(rr2.x * tf, rr2.y * tf);
    }
}

// score[i] = sum_d | t[i][d] - dis[i]*(adj@(dis*t))[i][d] |; a_s persists
template<int NPGc>
__device__ void score_ph(int q, const float* __restrict__ tg,
                         const float* __restrict__ disg,
                         float* __restrict__ scoreg, float* SCR) {
    constexpr int R = NPGc / 4;
    constexpr int AP = NPGc + 4;
    constexpr int NR = R / 16;
    float* v_s = SCR;
    float* a_s = SCR + A_ADJ;
    int tid = threadIdx.x, w = tid >> 5, lane = tid & 31;
    int rowb = q * R;

    { const float4* tg4 = (const float4*)tg; float4* v_s4 = (float4*)v_s;
      #pragma unroll 4
      for (int i = tid; i < NPGc * 16; i += NTHREADS) {
          float4 t4 = tg4[i];
          float dk = disg[i >> 4];
          v_s4[i] = make_float4(t4.x * dk, t4.y * dk, t4.z * dk, t4.w * dk);
      } }
    __syncthreads();

    u64 acc[NR];
    #pragma unroll
    for (int r = 0; r < NR; r++) acc[r] = 0ull;
    #pragma unroll 2
    for (int k0 = 0; k0 < NPGc; k0 += 4) {
        float4 a[NR];
        #pragma unroll
        for (int r = 0; r < NR; r++)
            a[r] = *(const float4*)(a_s + (w * NR + r) * AP + k0);
        u64 vv[4];
        #pragma unroll
        for (int j = 0; j < 4; j++)
            vv[j] = *(const u64*)(v_s + (k0 + j) * 64 + 2 * lane);
        #pragma unroll
        for (int r = 0; r < NR; r++) {
            acc[r] = f2fma(pk2(a[r].x), vv[0], acc[r]);
            acc[r] = f2fma(pk2(a[r].y), vv[1], acc[r]);
            acc[r] = f2fma(pk2(a[r].z), vv[2], acc[r]);
            acc[r] = f2fma(pk2(a[r].w), vv[3], acc[r]);
        }
    }
    #pragma unroll
    for (int r = 0; r < NR; r++) {
        int row = rowb + w * NR + r;
        float2 y = upk(acc[r]);
        float disr = disg[row];
        float2 tv = *(const float2*)(tg + (size_t)row * 64 + 2 * lane);
        float sc = wred32(fabsf(tv.x - disr * y.x) + fabsf(tv.y - disr * y.y));
        if (lane == 0) scoreg[row] = sc;
    }
}

// register+shuffle bitonic: descending by score, ties -> smaller index first.
__device__ void topk(int n, int kk, const float* __restrict__ scoreg,
                     float* SORTS, int* SORTID, int* SELS, float* VALS) {
    int tid = threadIdx.x;
    bool act = tid < n;
    float s = act ? scoreg[tid] : 0.f;
    int   id = tid;
    for (int ksz = 2; ksz <= n; ksz <<= 1) {
        for (int j = ksz >> 1; j > 0; j >>= 1) {
            float so = 0.f; int ido = 0;
            if (j >= 32) {
                __syncthreads();
                if (act) { SORTS[tid] = s; SORTID[tid] = id; }
                __syncthreads();
                if (act) { so = SORTS[tid ^ j]; ido = SORTID[tid ^ j]; }
            } else if (act) {
                so = __shfl_xor_sync(0xffffffffu, s, j);
                ido = __shfl_xor_sync(0xffffffffu, id, j);
            }
            if (act) {
                bool asc = (tid & ksz) == 0;
                bool low = (tid & j) == 0;
                bool first_mine = (s > so) || (s == so && id < ido);
                if (first_mine != (low == asc)) { s = so; id = ido; }
            }
        }
    }
    __syncthreads();
    if (tid < kk) { SELS[tid] = id; VALS[tid] = s; }
    __syncthreads();
}

// pool ALL kk rows redundantly; results -> smem TB + SA1/SA2
__device__ void pool(int kk, const float* __restrict__ tg, const float* __restrict__ att,
                     float* __restrict__ tB_s, float* SA1, float* SA2,
                     const int* SELS, const float* VALS) {
    int tid = threadIdx.x, hw = tid >> 4, l4 = (tid & 15) << 2;
    float4 at1 = *(const float4*)(att + l4);
    float4 at2 = *(const float4*)(att + 64 + l4);
    for (int it = 0; it < (kk >> 5); it++) {
        int i = (it << 5) + hw;
        int li = SELS[i];
        float tn = tanhf(VALS[i]);
        float4 xv = *(const float4*)(tg + (size_t)li * 64 + l4);
        xv = make_float4(xv.x * tn, xv.y * tn, xv.z * tn, xv.w * tn);
        *(float4*)(tB_s + i * 64 + l4) = xv;
        float r1 = hwred16(dot4(xv, at1));
        float r2 = hwred16(dot4(xv, at2));
        if ((tid & 15) == 0) { SA1[i] = r1; SA2[i] = r2; }
    }
    __syncthreads();
}

// L2 adjacency: global (for L3 gather) AND own quarter rows to smem a_s
template<int KK>
__device__ void new_adj_gl_sm(const float* __restrict__ adjsrc, int npg, int q,
                              const float* SA1, const float* SA2, const int* SELS,
                              float* __restrict__ adjdst, float* a_dst) {
    int tid = threadIdx.x;
    constexpr int QN = KK / 4;
    constexpr int APd = KK + 4;
    for (int idx = tid; idx < QN * KK; idx += NTHREADS) {
        int il = idx / KK;
        int i = q * QN + il;
        int j = idx & (KK - 1);
        float e = SA1[i] + SA2[j];
        float val = fmaxf(e, 0.f) + adjsrc[(size_t)SELS[i] * npg + SELS[j]];
        adjdst[(size_t)i * KK + j] = val;
        a_dst[il * APd + j] = val;
    }
}

// L3 adjacency: smem only (own quarter rows are the only ones ever read)
template<int KK>
__device__ void new_adj_sm(const float* __restrict__ adjsrc, int npg, int q,
                           const float* SA1, const float* SA2, const int* SELS,
                           float* a_dst) {
    int tid = threadIdx.x;
    constexpr int QN = KK / 4;
    constexpr int APd = KK + 4;
    for (int idx = tid; idx < QN * KK; idx += NTHREADS) {
        int il = idx / KK;
        int i = q * QN + il;
        int j = idx & (KK - 1);
        float e = SA1[i] + SA2[j];
        a_dst[il * APd + j] =
            fmaxf(e, 0.f) + adjsrc[(size_t)SELS[i] * npg + SELS[j]];
    }
}

// generic over global OR shared tg pointer
__device__ void readout(const float* __restrict__ tg, int kk, float* XR, float* RS) {
    int tid = threadIdx.x;
    int d = tid & 63, grp = tid >> 6;
    float mx = -INFINITY, sm2 = 0.f;
    for (int i = grp; i < kk; i += 8) {
        float v = tg[(size_t)i * 64 + d];
        mx = fmaxf(mx, v); sm2 += v;
    }
    RS[grp * 64 + d] = mx;
    RS[512 + grp * 64 + d] = sm2;
    __syncthreads();
    if (tid < 64) {
        float m = -INFINITY, s = 0.f;
        #pragma unroll
        for (int g2 = 0; g2 < 8; g2++) {
            m = fmaxf(m, RS[g2 * 64 + tid]);
            s += RS[512 + g2 * 64 + tid];
        }
        XR[tid] = m; XR[64 + tid] = s / (float)kk;
    }
    __syncthreads();
}

// ---------------- megakernel ----------------
extern __shared__ float sm[];

__global__ void __cluster_dims__(4, 1, 1) __launch_bounds__(NTHREADS, 1)
mega_kernel(const float* __restrict__ x, const int* __restrict__ ei, int E,
            const float* __restrict__ W1, const float* __restrict__ b1,
            const float* __restrict__ W2, const float* __restrict__ b2,
            const float* __restrict__ W3, const float* __restrict__ b3,
            const float* __restrict__ att1, const float* __restrict__ att2,
            const float* __restrict__ lw1, const float* __restrict__ lb1,
            const float* __restrict__ lw2, const float* __restrict__ lb2,
            const float* __restrict__ lw3, const float* __restrict__ lb3,
            float* __restrict__ out) {
    float* HB = sm + SM_HB;
    float* HBN2 = sm + SM_HBN2;
    float* RED = sm + SM_RED;
    float* SORTS = sm + SM_SORTS;
    int*   SORTID = (int*)(sm + SM_SORTID);
    int*   SELS = (int*)(sm + SM_SELS);
    float* VALS = sm + SM_VALS;
    float* SA1 = sm + SM_SA1;
    float* SA2 = sm + SM_SA2;
    float* X1R = sm + SM_X1R;
    float* X2R = sm + SM_X2R;
    float* X3R = sm + SM_X3R;
    float* XN = sm + SM_XN;
    float* MLP0 = sm + SM_MLP0;
    float* MLP1 = sm + SM_MLP1;
    float* MLP2 = sm + SM_MLP2;
    float* SCR = sm + SM_SCR;
    float* TB  = sm + SM_TB;    // pooled features, smem-resident

    int g = blockIdx.x >> 2, q = blockIdx.x & 3, tid = threadIdx.x;

    float* adj1g = g_adj1 + (size_t)g * 256 * 256;
    float* adj2g = g_adj2 + (size_t)g * 128 * 128;
    float* vg = g_v + (size_t)g * GS * 64;
    float* tAg = g_tA + (size_t)g * GS * 64;
    float* disg = g_dis + (size_t)g * GS;
    float* scoreg = g_score + (size_t)g * GS;

    // hb = proj(expmap0(b_l))
    {
        int l = tid >> 6, d = tid & 63;
        float u = (l < 3) ? ((l == 0 ? b1 : (l == 1 ? b2 : b3))[d]) : 0.f;
        float un2 = red64(u * u, RED);
        if (l < 3) {
            float un = fmaxf(sqrtf(un2), MIN_NORM);
            float tu = tanhf(un);
            float s0 = tu / un, pn = tu;
            if (tu > MAXN) { s0 *= MAXN / tu; pn = MAXN; }
            HB[l * 64 + d] = u * s0;
            if (d == 0) HBN2[l] = pn * pn;
        }
    }

    // sx (own quarter only, cooperative) -> global; published by the arrive below
    {
        int node = tid >> 3, j = tid & 7;
        int gn = g * NPG + q * 64 + node;
        const float4* xr = (const float4*)(x + (size_t)gn * 128 + j * 16);
        float s = 0.f;
        #pragma unroll
        for (int p = 0; p < 4; p++) { float4 v4 = xr[p]; s += v4.x + v4.y + v4.z + v4.w; }
        s += __shfl_xor_sync(0xffffffffu, s, 4);
        s += __shfl_xor_sync(0xffffffffu, s, 2);
        s += __shfl_xor_sync(0xffffffffu, s, 1);
        if (j == 0) g_sx[gn] = s;
    }
    pre_agg<128, 64>(x + (size_t)(g * NPG + q * 64) * 128, W1, HB, HBN2[0],
                     vg + (size_t)(q * 64) * 64, SCR, XN);
    CARRIVE();   // publishes g_sx + v quarter
    // local-only zeroing overlapped with the cluster barrier
    {
        float4* asm4 = (float4*)(SCR + A_ADJ);
        #pragma unroll 4
        for (int i = tid; i < 64 * 260 / 4; i += NTHREADS)
            asm4[i] = make_float4(0.f, 0.f, 0.f, 0.f);
        float4* dst = (float4*)(adj1g + (size_t)q * 64 * 256);
        #pragma unroll 4
        for (int i = tid; i < 64 * 256 / 4; i += NTHREADS)
            dst[i] = make_float4(0.f, 0.f, 0.f, 0.f);
    }
    CWAIT();
    __syncthreads();   // order zeroing (between arrive/wait) before scatter

    // scatter: scan this graph's edges, keep rows in own quarter;
    // write smem a_s (for agg/score) AND global adj1 (for top-k gather).
    {
        int Eg = E / NB;
        float* a_s = SCR + A_ADJ;
        for (int t = tid; t < Eg; t += NTHREADS) {
            int e = g * Eg + t;
            int rf = ei[e], cf = ei[E + e];
            int r = rf & 255, c = cf & 255;
            if ((r >> 6) == q) {
                float wv = 0.5f * (g_sx[rf] + g_sx[cf]);
                a_s[(r & 63) * 260 + c] = wv;
                adj1g[(size_t)r * 256 + c] = wv;
            }
        }
    }

    agg<256>(q, vg, tAg, disg, SCR);
    CSYNC();
    score_ph<256>(q, tAg, disg, scoreg, SCR);
    CSYNC();
    topk(256, 128, scoreg, SORTS, SORTID, SELS, VALS);
    pool(128, tAg, att1, TB, SA1, SA2, SELS, VALS);
    new_adj_gl_sm<128>(adj1g, 256, q, SA1, SA2, SELS, adj2g, SCR + A_ADJ);
    pre_agg<64, 32>(TB + q * 32 * 64, W2, HB + 64, HBN2[1],
                    vg + (size_t)(q * 32) * 64, SCR, XN);
    CARRIVE();   // publishes v quarter (L2)
    readout(TB, 128, X1R, SCR);   // local smem only; overlapped with barrier
    CWAIT();

    agg<128>(q, vg, tAg, disg, SCR);
    CSYNC();
    score_ph<128>(q, tAg, disg, scoreg, SCR);
    CSYNC();
    topk(128, 64, scoreg, SORTS, SORTID, SELS, VALS);
    pool(64, tAg, att2, TB, SA1, SA2, SELS, VALS);
    new_adj_sm<64>(adj2g, 128, q, SA1, SA2, SELS, SCR + A_ADJ);
    pre_agg<64, 16>(TB + q * 16 * 64, W3, HB + 128, HBN2[2],
                    vg + (size_t)(q * 16) * 64, SCR, XN);
    CARRIVE();   // publishes v quarter (L3)
    readout(TB, 64, X2R, SCR);    // local smem only; overlapped with barrier
    CWAIT();

    agg<64>(q, vg, tAg, disg, SCR);
    CSYNC();
    readout(tAg, 64, X3R, SCR);

    // MLP head (redundant per CTA; q==0 writes)
    if (tid < 128)
        MLP0[tid] = fmaxf(X1R[tid], 0.f) + fmaxf(X2R[tid], 0.f) + fmaxf(X3R[tid], 0.f);
    __syncthreads();
    if (tid < 64) {
        float acc = lb1[tid];
        #pragma unroll 8
        for (int k = 0; k < 128; k++) acc += lw1[tid * 128 + k] * MLP0[k];
        MLP1[tid] = fmaxf(acc, 0.f);
    }
    __syncthreads();
    if (tid < 32) {
        float acc = lb2[tid];
        #pragma unroll 8
        for (int k = 0; k < 64; k++) acc += lw2[tid * 64 + k] * MLP1[k];
        MLP2[tid] = fmaxf(acc, 0.f);
    }
    __syncthreads();
    if (tid == 0 && q == 0) {
        float l[NCLASS];
        float m = -INFINITY;
        for (int j = 0; j < NCLASS; j++) {
            float acc = lb3[j];
            for (int k = 0; k < 32; k++) acc += lw3[j * 32 + k] * MLP2[k];
            l[j] = acc;
            m = fmaxf(m, acc);
        }
        float s = 0.f;
        for (int j = 0; j < NCLASS; j++) s += expf(l[j] - m);
        float lse = m + logf(s);
        for (int j = 0; j < NCLASS; j++) out[g * NCLASS + j] = l[j] - lse;
    }
}

// ---------------- launch ----------------
extern "C" void kernel_launch(void* const* d_in, const int* in_sizes, int n_in,
                              void* d_out, int out_size) {
    const float* x    = (const float*)d_in[0];
    const int*   ei   = (const int*)d_in[1];
    const float* W1   = (const float*)d_in[2];
    const float* b1   = (const float*)d_in[3];
    const float* W2   = (const float*)d_in[4];
    const float* b2   = (const float*)d_in[5];
    const float* W3   = (const float*)d_in[6];
    const float* b3   = (const float*)d_in[7];
    const float* att1 = (const float*)d_in[8];
    const float* att2 = (const float*)d_in[9];
    const float* lw1  = (const float*)d_in[10];
    const float* lb1  = (const float*)d_in[11];
    const float* lw2  = (const float*)d_in[12];
    const float* lb2  = (const float*)d_in[13];
    const float* lw3  = (const float*)d_in[14];
    const float* lb3  = (const float*)d_in[15];

    int E = in_sizes[1] / 2;

    cudaFuncSetAttribute(mega_kernel, cudaFuncAttributeMaxDynamicSharedMemorySize, SMEM_BYTES);
    mega_kernel<<<GRID, NTHREADS, SMEM_BYTES>>>(
        x, ei, E, W1, b1, W2, b2, W3, b3, att1, att2,
        lw1, lb1, lw2, lb2, lw3, lb3, (float*)d_out);
}

// round 16
// speedup vs baseline: 1.0285x; 1.0285x over previous
#include <cuda_runtime.h>
#include <cuda_bf16.h>
#include <math.h>

#define NB    32
#define NPG   256
#define GS    256
#define NCLASS 6
#define MIN_NORM 1e-15f
#define MAXN 0.996f

#define NTHREADS 512
#define GRID     (NB * 4)

typedef unsigned long long u64;

// ---------------- global scratch ----------------
__device__ float g_sx[NB * NPG];
__device__ float g_adj1[NB * 256 * 256];
__device__ float g_adj2[NB * 128 * 128];
__device__ float g_v  [NB * GS * 64];
__device__ float g_tA [NB * GS * 64];
__device__ float g_dis[NB * GS];
__device__ float g_score[NB * GS];

// ---------------- smem layout (floats) ----------------
#define SM_HB     0        // 192
#define SM_HBN2   192      // 4
#define SM_RED    196      // 16
#define SM_SORTS  212      // 256
#define SM_SORTID 468      // 256 (int)
#define SM_SELS   724      // 128 (int)
#define SM_VALS   852      // 128
#define SM_SA1    980      // 128
#define SM_SA2    1108     // 128
#define SM_X1R    1236     // 128
#define SM_X2R    1364     // 128
#define SM_X3R    1492     // 128
#define SM_XN     1620     // 64
#define SM_MLP0   1684     // 128
#define SM_MLP1   1812     // 64
#define SM_MLP2   1876     // 32
#define SM_SCR    1920
// SCR-relative union:
//   a_s at A_ADJ=17504:
//     L1: 64*260=16640 (scatter)  L2: 32*132 (new_adj_gl_sm)  L3: 16*68 (new_adj_sm)
//   v_s stagings [0,16384); pre_agg Wt+xh [0,17408); readout scratch [0,1024)
// TB (pooled features, smem-resident) after a_s: 128*64 floats
#define A_ADJ  17504
#define SM_TB  (1920 + A_ADJ + 64 * 260)
#define SM_TOTALF (SM_TB + 128 * 64)
#define SMEM_BYTES (SM_TOTALF * 4)

#define CARRIVE() asm volatile("barrier.cluster.arrive.aligned;" ::: "memory")
#define CWAIT()   asm volatile("barrier.cluster.wait.aligned;"   ::: "memory")
#define CSYNC() do { CARRIVE(); CWAIT(); } while (0)

// ---------------- helpers (EXACT math & EXACT reduction orders — everything
// upstream of topk must be bit-faithful: fast approximations (R7) AND even a
// changed summation order in deg (R13) flipped top-k selections and broke
// correctness. Do not touch any arithmetic or reduction order here.
// Also: keep the Wt transpose in its original (conflicted) form — the
// "conflict-free" remap (R14) made the global read uncoalesced and was
// slower.) -------------------------------------------------------------
__device__ __forceinline__ float artanh_f(float x) {
    x = fminf(fmaxf(x, -1.0f + 1e-7f), 1.0f - 1e-7f);
    return 0.5f * (log1pf(x) - log1pf(-x));
}
__device__ __forceinline__ float wred32(float v) {
    #pragma unroll
    for (int o = 16; o > 0; o >>= 1) v += __shfl_xor_sync(0xffffffffu, v, o);
    return v;
}
__device__ __forceinline__ float hwred16(float v) {
    v += __shfl_xor_sync(0xffffffffu, v, 8);
    v += __shfl_xor_sync(0xffffffffu, v, 4);
    v += __shfl_xor_sync(0xffffffffu, v, 2);
    v += __shfl_xor_sync(0xffffffffu, v, 1);
    return v;
}
__device__ __forceinline__ float red64(float v, float* red) {
    int tid = threadIdx.x;
    #pragma unroll
    for (int o = 16; o > 0; o >>= 1) v += __shfl_xor_sync(0xffffffffu, v, o);
    if ((tid & 31) == 0) red[tid >> 5] = v;
    __syncthreads();
    float r = red[(tid >> 6) * 2] + red[(tid >> 6) * 2 + 1];
    __syncthreads();
    return r;
}
__device__ __forceinline__ float dot4(float4 a, float4 b) {
    return a.x * b.x + a.y * b.y + a.z * b.z + a.w * b.w;
}
__device__ __forceinline__ u64 pk2(float a) {
    u64 r; asm("mov.b64 %0,{%1,%1};" : "=l"(r) : "f"(a)); return r;
}
__device__ __forceinline__ u64 f2fma(u64 a, u64 b, u64 c) {
    u64 d; asm("fma.rn.f32x2 %0,%1,%2,%3;" : "=l"(d) : "l"(a), "l"(b), "l"(c)); return d;
}
__device__ __forceinline__ float2 upk(u64 a) {
    float2 f; asm("mov.b64 {%0,%1},%2;" : "=f"(f.x), "=f"(f.y) : "l"(a)); return f;
}

// ---------------- phases ----------------

// v = logmap0(proj(mobius_add(proj(mobius_matvec(W, to_hyp(in))), hb)))
// `in`/`vout` may be global OR shared (generic pointers).
template<int IN, int NQ>
__device__ void pre_agg(const float* __restrict__ in,
                        const float* __restrict__ W,
                        const float* HBl, float hbn2v,
                        float* __restrict__ vout, float* SCR, float* XN) {
    constexpr int XHP = IN + 8;
    constexpr int NR = NQ / 16;
    float* Wt = SCR;
    float* xh = SCR + IN * 68;
    int tid = threadIdx.x, w = tid >> 5, lane = tid & 31;

    for (int idx = tid; idx < 64 * IN; idx += NTHREADS) {
        int o = idx / IN, k = idx & (IN - 1);
        Wt[k * 68 + o] = W[idx];
    }
    if (tid < NQ * 8) {
        int node = tid >> 3, j = tid & 7;
        constexpr int F4 = IN / 32;
        const float4* ur = (const float4*)(in + (size_t)node * IN) + j * F4;
        float4 u[F4];
        float s = 0.f;
        #pragma unroll
        for (int t = 0; t < F4; t++) { u[t] = ur[t]; s += dot4(u[t], u[t]); }
        s += __shfl_xor_sync(0xffffffffu, s, 4);
        s += __shfl_xor_sync(0xffffffffu, s, 2);
        s += __shfl_xor_sync(0xffffffffu, s, 1);
        float un = fmaxf(sqrtf(s), MIN_NORM);
        float tu = tanhf(un);
        float s0 = tu / un, xn = tu;
        if (tu > MAXN) { s0 *= MAXN / tu; xn = MAXN; }
        float4* xrow = (float4*)(xh + node * XHP) + j * F4;
        #pragma unroll
        for (int t = 0; t < F4; t++)
            xrow[t] = make_float4(u[t].x * s0, u[t].y * s0, u[t].z * s0, u[t].w * s0);
        if (j == 0) XN[node] = xn;
    }
    __syncthreads();

    u64 acc[NR];
    #pragma unroll
    for (int r = 0; r < NR; r++) acc[r] = 0ull;
    #pragma unroll 2
    for (int k0 = 0; k0 < IN; k0 += 4) {
        float4 a[NR];
        #pragma unroll
        for (int r = 0; r < NR; r++)
            a[r] = *(const float4*)(xh + (w * NR + r) * XHP + k0);
        u64 vv[4];
        #pragma unroll
        for (int j = 0; j < 4; j++)
            vv[j] = *(const u64*)(Wt + (k0 + j) * 68 + 2 * lane);
        #pragma unroll
        for (int r = 0; r < NR; r++) {
            acc[r] = f2fma(pk2(a[r].x), vv[0], acc[r]);
            acc[r] = f2fma(pk2(a[r].y), vv[1], acc[r]);
            acc[r] = f2fma(pk2(a[r].z), vv[2], acc[r]);
            acc[r] = f2fma(pk2(a[r].w), vv[3], acc[r]);
        }
    }
    float2 hb2 = *(const float2*)(HBl + 2 * lane);
    #pragma unroll
    for (int r = 0; r < NR; r++) {
        int node = w * NR + r;
        float2 mx = upk(acc[r]);
        float mxn = fmaxf(sqrtf(wred32(mx.x * mx.x + mx.y * mx.y)), MIN_NORM);
        float xnv = XN[node];
        float qv = mxn / xnv * artanh_f(xnv);
        float tq = tanhf(qv);
        float s1 = tq / mxn, hn = tq;
        if (tq > MAXN) { s1 *= MAXN / tq; hn = MAXN; }
        float2 hv = make_float2(mx.x * s1, mx.y * s1);
        float xy = wred32(hv.x * hb2.x + hv.y * hb2.y);
        float x2 = hn * hn, y2 = hbn2v;
        float ca = 1.f + 2.f * xy + y2, cb = 1.f - x2;
        float den = fmaxf(1.f + 2.f * xy + x2 * y2, MIN_NORM);
        float2 m = make_float2((ca * hv.x + cb * hb2.x) / den,
                               (ca * hv.y + cb * hb2.y) / den);
        float mn = fmaxf(sqrtf(wred32(m.x * m.x + m.y * m.y)), MIN_NORM);
        float s2 = 1.f, pn = mn;
        if (mn > MAXN) { s2 = MAXN / mn; pn = MAXN; }
        float lf = artanh_f(pn) / pn * s2;
        *(float2*)(vout + (size_t)node * 64 + 2 * lane) =
            make_float2(m.x * lf, m.y * lf);
    }
}

// adj@v -> nonlinear chain -> t; also dis for own quarter rows. a_s pre-filled.
// (deg pass MUST stay exactly in this lane-strided shuffle order — R13.)
template<int NPGc>
__device__ void agg(int q, const float* __restrict__ vg, float* __restrict__ tg,
                    float* __restrict__ disg, float* SCR) {
    constexpr int R = NPGc / 4;
    constexpr int AP = NPGc + 4;
    constexpr int NR = R / 16;
    float* v_s = SCR;
    float* a_s = SCR + A_ADJ;
    int tid = threadIdx.x, w = tid >> 5, lane = tid & 31;
    int rowb = q * R;

    { const float4* vg4 = (const float4*)vg; float4* v_s4 = (float4*)v_s;
      #pragma unroll 4
      for (int i = tid; i < NPGc * 16; i += NTHREADS) v_s4[i] = vg4[i]; }
    __syncthreads();

    #pragma unroll
    for (int rr = 0; rr < NR; rr++) {
        int r = w * NR + rr;
        float s = 0.f;
        #pragma unroll 4
        for (int k = lane; k < NPGc; k += 32) s += a_s[r * AP + k];
        s = wred32(s);
        if (lane == 0) disg[rowb + r] = (s > 0.f) ? (1.f / sqrtf(s)) : 0.f;
    }

    u64 acc[NR];
    #pragma unroll
    for (int r = 0; r < NR; r++) acc[r] = 0ull;
    #pragma unroll 2
    for (int k0 = 0; k0 < NPGc; k0 += 4) {
        float4 a[NR];
        #pragma unroll
        for (int r = 0; r < NR; r++)
            a[r] = *(const float4*)(a_s + (w * NR + r) * AP + k0);
        u64 vv[4];
        #pragma unroll
        for (int j = 0; j < 4; j++)
            vv[j] = *(const u64*)(v_s + (k0 + j) * 64 + 2 * lane);
        #pragma unroll
        for (int r = 0; r < NR; r++) {
            acc[r] = f2fma(pk2(a[r].x), vv[0], acc[r]);
            acc[r] = f2fma(pk2(a[r].y), vv[1], acc[r]);
            acc[r] = f2fma(pk2(a[r].z), vv[2], acc[r]);
            acc[r] = f2fma(pk2(a[r].w), vv[3], acc[r]);
        }
    }
    #pragma unroll
    for (int r = 0; r < NR; r++) {
        float2 y = upk(acc[r]);
        float an = fmaxf(sqrtf(wred32(y.x * y.x + y.y * y.y)), MIN_NORM);
        float ta = tanhf(an);
        float s1 = ta / an, hn = ta;
        if (ta > MAXN) { s1 *= MAXN / ta; hn = MAXN; }
        float lf = artanh_f(hn) / hn * s1;
        float2 rr2 = make_float2(fmaxf(y.x * lf, 0.f), fmaxf(y.y * lf, 0.f));
        float rn = fmaxf(sqrtf(wred32(rr2.x * rr2.x + rr2.y * rr2.y)), MIN_NORM);
        float tr = tanhf(rn);
        float s2 = tr / rn, en = tr;
        if (tr > MAXN) { s2 *= MAXN / tr; en = MAXN; }
        float tf = artanh_f(en) / en * s2;
        *(float2*)(tg + (size_t)(rowb + w * NR + r) * 64 + 2 * lane) =
            make_float2(rr2.x * tf, rr2.y * tf);
    }
}

// score[i] = sum_d | t[i][d] - dis[i]*(adj@(dis*t))[i][d] |; a_s persists
template<int NPGc>
__device__ void score_ph(int q, const float* __restrict__ tg,
                         const float* __restrict__ disg,
                         float* __restrict__ scoreg, float* SCR) {
    constexpr int R = NPGc / 4;
    constexpr int AP = NPGc + 4;
    constexpr int NR = R / 16;
    float* v_s = SCR;
    float* a_s = SCR + A_ADJ;
    int tid = threadIdx.x, w = tid >> 5, lane = tid & 31;
    int rowb = q * R;

    { const float4* tg4 = (const float4*)tg; float4* v_s4 = (float4*)v_s;
      #pragma unroll 4
      for (int i = tid; i < NPGc * 16; i += NTHREADS) {
          float4 t4 = tg4[i];
          float dk = disg[i >> 4];
          v_s4[i] = make_float4(t4.x * dk, t4.y * dk, t4.z * dk, t4.w * dk);
      } }
    __syncthreads();

    u64 acc[NR];
    #pragma unroll
    for (int r = 0; r < NR; r++) acc[r] = 0ull;
    #pragma unroll 2
    for (int k0 = 0; k0 < NPGc; k0 += 4) {
        float4 a[NR];
        #pragma unroll
        for (int r = 0; r < NR; r++)
            a[r] = *(const float4*)(a_s + (w * NR + r) * AP + k0);
        u64 vv[4];
        #pragma unroll
        for (int j = 0; j < 4; j++)
            vv[j] = *(const u64*)(v_s + (k0 + j) * 64 + 2 * lane);
        #pragma unroll
        for (int r = 0; r < NR; r++) {
            acc[r] = f2fma(pk2(a[r].x), vv[0], acc[r]);
            acc[r] = f2fma(pk2(a[r].y), vv[1], acc[r]);
            acc[r] = f2fma(pk2(a[r].z), vv[2], acc[r]);
            acc[r] = f2fma(pk2(a[r].w), vv[3], acc[r]);
        }
    }
    #pragma unroll
    for (int r = 0; r < NR; r++) {
        int row = rowb + w * NR + r;
        float2 y = upk(acc[r]);
        float disr = disg[row];
        float2 tv = *(const float2*)(tg + (size_t)row * 64 + 2 * lane);
        float sc = wred32(fabsf(tv.x - disr * y.x) + fabsf(tv.y - disr * y.y));
        if (lane == 0) scoreg[row] = sc;
    }
}

// register+shuffle bitonic: descending by score, ties -> smaller index first.
__device__ void topk(int n, int kk, const float* __restrict__ scoreg,
                     float* SORTS, int* SORTID, int* SELS, float* VALS) {
    int tid = threadIdx.x;
    bool act = tid < n;
    float s = act ? scoreg[tid] : 0.f;
    int   id = tid;
    for (int ksz = 2; ksz <= n; ksz <<= 1) {
        for (int j = ksz >> 1; j > 0; j >>= 1) {
            float so = 0.f; int ido = 0;
            if (j >= 32) {
                __syncthreads();
                if (act) { SORTS[tid] = s; SORTID[tid] = id; }
                __syncthreads();
                if (act) { so = SORTS[tid ^ j]; ido = SORTID[tid ^ j]; }
            } else if (act) {
                so = __shfl_xor_sync(0xffffffffu, s, j);
                ido = __shfl_xor_sync(0xffffffffu, id, j);
            }
            if (act) {
                bool asc = (tid & ksz) == 0;
                bool low = (tid & j) == 0;
                bool first_mine = (s > so) || (s == so && id < ido);
                if (first_mine != (low == asc)) { s = so; id = ido; }
            }
        }
    }
    __syncthreads();
    if (tid < kk) { SELS[tid] = id; VALS[tid] = s; }
    __syncthreads();
}

// pool ALL kk rows redundantly; results -> smem TB + SA1/SA2
__device__ void pool(int kk, const float* __restrict__ tg, const float* __restrict__ att,
                     float* __restrict__ tB_s, float* SA1, float* SA2,
                     const int* SELS, const float* VALS) {
    int tid = threadIdx.x, hw = tid >> 4, l4 = (tid & 15) << 2;
    float4 at1 = *(const float4*)(att + l4);
    float4 at2 = *(const float4*)(att + 64 + l4);
    for (int it = 0; it < (kk >> 5); it++) {
        int i = (it << 5) + hw;
        int li = SELS[i];
        float tn = tanhf(VALS[i]);
        float4 xv = *(const float4*)(tg + (size_t)li * 64 + l4);
        xv = make_float4(xv.x * tn, xv.y * tn, xv.z * tn, xv.w * tn);
        *(float4*)(tB_s + i * 64 + l4) = xv;
        float r1 = hwred16(dot4(xv, at1));
        float r2 = hwred16(dot4(xv, at2));
        if ((tid & 15) == 0) { SA1[i] = r1; SA2[i] = r2; }
    }
    __syncthreads();
}

// L2 adjacency: global (for L3 gather) AND own quarter rows to smem a_s
template<int KK>
__device__ void new_adj_gl_sm(const float* __restrict__ adjsrc, int npg, int q,
                              const float* SA1, const float* SA2, const int* SELS,
                              float* __restrict__ adjdst, float* a_dst) {
    int tid = threadIdx.x;
    constexpr int QN = KK / 4;
    constexpr int APd = KK + 4;
    for (int idx = tid; idx < QN * KK; idx += NTHREADS) {
        int il = idx / KK;
        int i = q * QN + il;
        int j = idx & (KK - 1);
        float e = SA1[i] + SA2[j];
        float val = fmaxf(e, 0.f) + adjsrc[(size_t)SELS[i] * npg + SELS[j]];
        adjdst[(size_t)i * KK + j] = val;
        a_dst[il * APd + j] = val;
    }
}

// L3 adjacency: smem only (own quarter rows are the only ones ever read)
template<int KK>
__device__ void new_adj_sm(const float* __restrict__ adjsrc, int npg, int q,
                           const float* SA1, const float* SA2, const int* SELS,
                           float* a_dst) {
    int tid = threadIdx.x;
    constexpr int QN = KK / 4;
    constexpr int APd = KK + 4;
    for (int idx = tid; idx < QN * KK; idx += NTHREADS) {
        int il = idx / KK;
        int i = q * QN + il;
        int j = idx & (KK - 1);
        float e = SA1[i] + SA2[j];
        a_dst[il * APd + j] =
            fmaxf(e, 0.f) + adjsrc[(size_t)SELS[i] * npg + SELS[j]];
    }
}

// generic over global OR shared tg pointer
__device__ void readout(const float* __restrict__ tg, int kk, float* XR, float* RS) {
    int tid = threadIdx.x;
    int d = tid & 63, grp = tid >> 6;
    float mx = -INFINITY, sm2 = 0.f;
    for (int i = grp; i < kk; i += 8) {
        float v = tg[(size_t)i * 64 + d];
        mx = fmaxf(mx, v); sm2 += v;
    }
    RS[grp * 64 + d] = mx;
    RS[512 + grp * 64 + d] = sm2;
    __syncthreads();
    if (tid < 64) {
        float m = -INFINITY, s = 0.f;
        #pragma unroll
        for (int g2 = 0; g2 < 8; g2++) {
            m = fmaxf(m, RS[g2 * 64 + tid]);
            s += RS[512 + g2 * 64 + tid];
        }
        XR[tid] = m; XR[64 + tid] = s / (float)kk;
    }
    __syncthreads();
}

// ---------------- megakernel ----------------
extern __shared__ float sm[];

__global__ void __cluster_dims__(4, 1, 1) __launch_bounds__(NTHREADS, 1)
mega_kernel(const float* __restrict__ x, const int* __restrict__ ei, int E,
            const float* __restrict__ W1, const float* __restrict__ b1,
            const float* __restrict__ W2, const float* __restrict__ b2,
            const float* __restrict__ W3, const float* __restrict__ b3,
            const float* __restrict__ att1, const float* __restrict__ att2,
            const float* __restrict__ lw1, const float* __restrict__ lb1,
            const float* __restrict__ lw2, const float* __restrict__ lb2,
            const float* __restrict__ lw3, const float* __restrict__ lb3,
            float* __restrict__ out) {
    float* HB = sm + SM_HB;
    float* HBN2 = sm + SM_HBN2;
    float* RED = sm + SM_RED;
    float* SORTS = sm + SM_SORTS;
    int*   SORTID = (int*)(sm + SM_SORTID);
    int*   SELS = (int*)(sm + SM_SELS);
    float* VALS = sm + SM_VALS;
    float* SA1 = sm + SM_SA1;
    float* SA2 = sm + SM_SA2;
    float* X1R = sm + SM_X1R;
    float* X2R = sm + SM_X2R;
    float* X3R = sm + SM_X3R;
    float* XN = sm + SM_XN;
    float* MLP0 = sm + SM_MLP0;
    float* MLP1 = sm + SM_MLP1;
    float* MLP2 = sm + SM_MLP2;
    float* SCR = sm + SM_SCR;
    float* TB  = sm + SM_TB;    // pooled features, smem-resident

    int g = blockIdx.x >> 2, q = blockIdx.x & 3, tid = threadIdx.x;

    float* adj1g = g_adj1 + (size_t)g * 256 * 256;
    float* adj2g = g_adj2 + (size_t)g * 128 * 128;
    float* vg = g_v + (size_t)g * GS * 64;
    float* tAg = g_tA + (size_t)g * GS * 64;
    float* disg = g_dis + (size_t)g * GS;
    float* scoreg = g_score + (size_t)g * GS;

    // hb = proj(expmap0(b_l))
    {
        int l = tid >> 6, d = tid & 63;
        float u = (l < 3) ? ((l == 0 ? b1 : (l == 1 ? b2 : b3))[d]) : 0.f;
        float un2 = red64(u * u, RED);
        if (l < 3) {
            float un = fmaxf(sqrtf(un2), MIN_NORM);
            float tu = tanhf(un);
            float s0 = tu / un, pn = tu;
            if (tu > MAXN) { s0 *= MAXN / tu; pn = MAXN; }
            HB[l * 64 + d] = u * s0;
            if (d == 0) HBN2[l] = pn * pn;
        }
    }

    // sx (own quarter only, cooperative) -> global; published by the arrive below
    {
        int node = tid >> 3, j = tid & 7;
        int gn = g * NPG + q * 64 + node;
        const float4* xr = (const float4*)(x + (size_t)gn * 128 + j * 16);
        float s = 0.f;
        #pragma unroll
        for (int p = 0; p < 4; p++) { float4 v4 = xr[p]; s += v4.x + v4.y + v4.z + v4.w; }
        s += __shfl_xor_sync(0xffffffffu, s, 4);
        s += __shfl_xor_sync(0xffffffffu, s, 2);
        s += __shfl_xor_sync(0xffffffffu, s, 1);
        if (j == 0) g_sx[gn] = s;
    }
    pre_agg<128, 64>(x + (size_t)(g * NPG + q * 64) * 128, W1, HB, HBN2[0],
                     vg + (size_t)(q * 64) * 64, SCR, XN);
    CARRIVE();   // publishes g_sx + v quarter
    // local-only zeroing overlapped with the cluster barrier
    {
        float4* asm4 = (float4*)(SCR + A_ADJ);
        #pragma unroll 4
        for (int i = tid; i < 64 * 260 / 4; i += NTHREADS)
            asm4[i] = make_float4(0.f, 0.f, 0.f, 0.f);
        float4* dst = (float4*)(adj1g + (size_t)q * 64 * 256);
        #pragma unroll 4
        for (int i = tid; i < 64 * 256 / 4; i += NTHREADS)
            dst[i] = make_float4(0.f, 0.f, 0.f, 0.f);
    }
    CWAIT();
    __syncthreads();   // order zeroing (between arrive/wait) before scatter

    // scatter: scan this graph's edges, keep rows in own quarter;
    // write smem a_s (for agg/score) AND global adj1 (for top-k gather).
    {
        int Eg = E / NB;
        float* a_s = SCR + A_ADJ;
        for (int t = tid; t < Eg; t += NTHREADS) {
            int e = g * Eg + t;
            int rf = ei[e], cf = ei[E + e];
            int r = rf & 255, c = cf & 255;
            if ((r >> 6) == q) {
                float wv = 0.5f * (g_sx[rf] + g_sx[cf]);
                a_s[(r & 63) * 260 + c] = wv;
                adj1g[(size_t)r * 256 + c] = wv;
            }
        }
    }

    agg<256>(q, vg, tAg, disg, SCR);
    CSYNC();
    score_ph<256>(q, tAg, disg, scoreg, SCR);
    CSYNC();
    topk(256, 128, scoreg, SORTS, SORTID, SELS, VALS);
    pool(128, tAg, att1, TB, SA1, SA2, SELS, VALS);
    new_adj_gl_sm<128>(adj1g, 256, q, SA1, SA2, SELS, adj2g, SCR + A_ADJ);
    pre_agg<64, 32>(TB + q * 32 * 64, W2, HB + 64, HBN2[1],
                    vg + (size_t)(q * 32) * 64, SCR, XN);
    CARRIVE();   // publishes v quarter (L2)
    readout(TB, 128, X1R, SCR);   // local smem only; overlapped with barrier
    CWAIT();

    agg<128>(q, vg, tAg, disg, SCR);
    CSYNC();
    score_ph<128>(q, tAg, disg, scoreg, SCR);
    CSYNC();
    topk(128, 64, scoreg, SORTS, SORTID, SELS, VALS);
    pool(64, tAg, att2, TB, SA1, SA2, SELS, VALS);
    new_adj_sm<64>(adj2g, 128, q, SA1, SA2, SELS, SCR + A_ADJ);
    pre_agg<64, 16>(TB + q * 16 * 64, W3, HB + 128, HBN2[2],
                    vg + (size_t)(q * 16) * 64, SCR, XN);
    CARRIVE();   // publishes v quarter (L3)
    readout(TB, 64, X2R, SCR);    // local smem only; overlapped with barrier
    CWAIT();

    agg<64>(q, vg, tAg, disg, SCR);
    CSYNC();
    readout(tAg, 64, X3R, SCR);

    // MLP head (redundant per CTA; q==0 writes)
    if (tid < 128)
        MLP0[tid] = fmaxf(X1R[tid], 0.f) + fmaxf(X2R[tid], 0.f) + fmaxf(X3R[tid], 0.f);
    __syncthreads();
    if (tid < 64) {
        float acc = lb1[tid];
        #pragma unroll 8
        for (int k = 0; k < 128; k++) acc += lw1[tid * 128 + k] * MLP0[k];
        MLP1[tid] = fmaxf(acc, 0.f);
    }
    __syncthreads();
    if (tid < 32) {
        float acc = lb2[tid];
        #pragma unroll 8
        for (int k = 0; k < 64; k++) acc += lw2[tid * 64 + k] * MLP1[k];
        MLP2[tid] = fmaxf(acc, 0.f);
    }
    __syncthreads();
    if (tid == 0 && q == 0) {
        float l[NCLASS];
        float m = -INFINITY;
        for (int j = 0; j < NCLASS; j++) {
            float acc = lb3[j];
            for (int k = 0; k < 32; k++) acc += lw3[j * 32 + k] * MLP2[k];
            l[j] = acc;
            m = fmaxf(m, acc);
        }
        float s = 0.f;
        for (int j = 0; j < NCLASS; j++) s += expf(l[j] - m);
        float lse = m + logf(s);
        for (int j = 0; j < NCLASS; j++) out[g * NCLASS + j] = l[j] - lse;
    }
}

// ---------------- launch ----------------
extern "C" void kernel_launch(void* const* d_in, const int* in_sizes, int n_in,
                              void* d_out, int out_size) {
    const float* x    = (const float*)d_in[0];
    const int*   ei   = (const int*)d_in[1];
    const float* W1   = (const float*)d_in[2];
    const float* b1   = (const float*)d_in[3];
    const float* W2   = (const float*)d_in[4];
    const float* b2   = (const float*)d_in[5];
    const float* W3   = (const float*)d_in[6];
    const float* b3   = (const float*)d_in[7];
    const float* att1 = (const float*)d_in[8];
    const float* att2 = (const float*)d_in[9];
    const float* lw1  = (const float*)d_in[10];
    const float* lb1  = (const float*)d_in[11];
    const float* lw2  = (const float*)d_in[12];
    const float* lb2  = (const float*)d_in[13];
    const float* lw3  = (const float*)d_in[14];
    const float* lb3  = (const float*)d_in[15];

    int E = in_sizes[1] / 2;

    cudaFuncSetAttribute(mega_kernel, cudaFuncAttributeMaxDynamicSharedMemorySize, SMEM_BYTES);
    mega_kernel<<<GRID, NTHREADS, SMEM_BYTES>>>(
        x, ei, E, W1, b1, W2, b2, W3, b3, att1, att2,
        lw1, lb1, lw2, lb2, lw3, lb3, (float*)d_out);
}